// round 14
// baseline (speedup 1.0000x reference)
#include <cuda_runtime.h>
#include <cuda_fp16.h>
#include <math.h>
#include <cstdint>

// Problem constants
#define D_DIM 1024
#define H_DIM 4096
#define E_NUM 8
#define MAXA  16384
#define NTOK  8192
#define WN4   ((E_NUM * H_DIM * D_DIM) / 4)
#define XN4   ((NTOK * D_DIM) / 4)

// GEMM tiling: 128-thread CTA, 4 warps (2x2), warp tile 64x64, BK=64, 2-stage cp.async
#define BM 128
#define BN 128
#define BK 64
#define NSTAGE 2
#define STAGE_BYTES 32768     // A 16KB + B 16KB
#define SMEM_DYN (NSTAGE * STAGE_BYTES + 2048)

// ---------------- device scratch ----------------
__device__ __half g_H[(size_t)MAXA * H_DIM];
__device__ __half g_W1c[(size_t)E_NUM * H_DIM * D_DIM];
__device__ __half g_W2c[(size_t)E_NUM * D_DIM * H_DIM];
__device__ __half g_Xc[(size_t)NTOK * D_DIM];
__device__ int    g_bucket[E_NUM * MAXA];
__device__ int    g_cnt[E_NUM];
__device__ float  g_wts[MAXA];

// ---------------- helpers ----------------
__device__ __forceinline__ uint32_t smem_u32(const void* p) {
    uint32_t a;
    asm("{ .reg .u64 t; cvta.to.shared.u64 t, %1; cvt.u32.u64 %0, t; }" : "=r"(a) : "l"(p));
    return a;
}
__device__ __forceinline__ float gelu_exact(float v) {
    return 0.5f * v * (1.0f + erff(v * 0.70710678118654752f));
}
__device__ __forceinline__ void mma_f16(float* d, const uint32_t* a, const uint32_t* b) {
    asm volatile(
        "mma.sync.aligned.m16n8k16.row.col.f32.f16.f16.f32 "
        "{%0,%1,%2,%3}, {%4,%5,%6,%7}, {%8,%9}, {%0,%1,%2,%3};"
        : "+f"(d[0]), "+f"(d[1]), "+f"(d[2]), "+f"(d[3])
        : "r"(a[0]), "r"(a[1]), "r"(a[2]), "r"(a[3]), "r"(b[0]), "r"(b[1]));
}
__device__ __forceinline__ void ldsm_x4(uint32_t* r, uint32_t addr) {
    asm volatile("ldmatrix.sync.aligned.m8n8.x4.shared.b16 {%0,%1,%2,%3}, [%4];"
                 : "=r"(r[0]), "=r"(r[1]), "=r"(r[2]), "=r"(r[3]) : "r"(addr));
}
__device__ __forceinline__ void cp_async16(uint32_t dst, const void* src) {
    asm volatile("cp.async.cg.shared.global [%0], [%1], 16;" :: "r"(dst), "l"(src));
}
#define CP_COMMIT() asm volatile("cp.async.commit_group;" ::: "memory")
#define CP_WAIT0()  asm volatile("cp.async.wait_group 0;" ::: "memory")

// swizzled byte offset: row r (0..127, 128B rows), slot s (0..7, 16B granules)
__device__ __forceinline__ uint32_t sw_off(int r, int s) {
    return (uint32_t)(r * 128 + ((s ^ (r & 7)) << 4));
}

// ---------------- one-shot prep: convert W1/W2/X to fp16, zero counters ----------------
__global__ void prep_kernel(const float4* __restrict__ W1,
                            const float4* __restrict__ W2,
                            const float4* __restrict__ X,
                            __half2* __restrict__ w1c,
                            __half2* __restrict__ w2c,
                            __half2* __restrict__ xc) {
    long long i = (long long)blockIdx.x * blockDim.x + threadIdx.x;
    if (i == 0) {
        #pragma unroll
        for (int e = 0; e < E_NUM; e++) g_cnt[e] = 0;
    }
    const float4* src;
    __half2* dst;
    long long j = i;
    if (i < WN4)                  { src = W1; dst = w1c; }
    else if (i < 2LL * WN4)       { src = W2; dst = w2c; j = i - WN4; }
    else if (i < 2LL * WN4 + XN4) { src = X;  dst = xc;  j = i - 2LL * WN4; }
    else return;
    float4 v = src[j];
    dst[2 * j + 0] = __floats2half2_rn(v.x, v.y);
    dst[2 * j + 1] = __floats2half2_rn(v.z, v.w);
}

// ---------------- gate ----------------
__global__ void gate_kernel(const float* __restrict__ x,
                            const float* __restrict__ Wg, int N) {
    int warp = (blockIdx.x * blockDim.x + threadIdx.x) >> 5;
    int lane = threadIdx.x & 31;
    if (warp >= N) return;
    const float* xr = x + (size_t)warp * D_DIM;
    float acc[E_NUM];
    #pragma unroll
    for (int e = 0; e < E_NUM; e++) acc[e] = 0.0f;
    for (int d = lane; d < D_DIM; d += 32) {
        float xv = xr[d];
        #pragma unroll
        for (int e = 0; e < E_NUM; e++) acc[e] += xv * Wg[e * D_DIM + d];
    }
    #pragma unroll
    for (int e = 0; e < E_NUM; e++)
        #pragma unroll
        for (int o = 16; o > 0; o >>= 1)
            acc[e] += __shfl_xor_sync(0xffffffffu, acc[e], o);
    if (lane == 0) {
        float m1 = -INFINITY, m2 = -INFINITY;
        int i1 = 0, i2 = 0;
        #pragma unroll
        for (int e = 0; e < E_NUM; e++) {
            float l = acc[e];
            if (l > m1)      { m2 = m1; i2 = i1; m1 = l; i1 = e; }
            else if (l > m2) { m2 = l; i2 = e; }
        }
        float e1 = expf(m2 - m1);
        float inv = 1.0f / (1.0f + e1);
        int a0 = warp * 2, a1 = warp * 2 + 1;
        g_wts[a0] = inv;
        g_wts[a1] = e1 * inv;
        int p0 = atomicAdd(&g_cnt[i1], 1);
        g_bucket[i1 * MAXA + p0] = a0;
        int p1 = atomicAdd(&g_cnt[i2], 1);
        g_bucket[i2 * MAXA + p1] = a1;
    }
}

// ---------------- fp16 mma.sync gathered GEMM, 64x64 warp tiles, 2-stage, 3 CTAs/SM ----------------
template <int KDIM, int NOUT, bool GELU_EPI>
__global__ __launch_bounds__(128, 3)
void moe_mma_kernel(const __half* __restrict__ Asrc,
                    const __half* __restrict__ W,
                    const float* __restrict__ bias,
                    float* __restrict__ out_final) {
    constexpr int NCH = KDIM / BK;

    extern __shared__ __align__(16) char dsm[];
    uint32_t sb = smem_u32(dsm);
    int*   sh_aidx = (int*)(dsm + NSTAGE * STAGE_BYTES);
    int*   sh_asrc = (int*)(dsm + NSTAGE * STAGE_BYTES + 512);
    float* sh_wt   = (float*)(dsm + NSTAGE * STAGE_BYTES + 1024);
    float* sh_bias = (float*)(dsm + NSTAGE * STAGE_BYTES + 1536);

    int e = blockIdx.z;
    int cnt = g_cnt[e];
    int m0 = blockIdx.y * BM;
    if (m0 >= cnt) return;
    int n0 = blockIdx.x * BN;
    int tid = threadIdx.x;

    {
        int mi = m0 + tid;
        int a = (mi < cnt) ? g_bucket[e * MAXA + mi] : -1;
        sh_aidx[tid] = a;
        sh_asrc[tid] = (a >= 0) ? (GELU_EPI ? (a >> 1) : a) : 0;
        sh_wt[tid]   = (!GELU_EPI && a >= 0) ? g_wts[a] : 0.0f;
        sh_bias[tid] = bias[(size_t)e * NOUT + n0 + tid];
    }
    __syncthreads();

    const __half* Wb = W + (size_t)e * NOUT * KDIM;

    // ---- loader mapping: slot = tid&7 (8 fp16), rows = (tid>>3) + 16j, j=0..7 ----
    int ls = tid & 7;
    int lr = tid >> 3;                 // 0..15
    uint32_t aoff[8], boff[8], dsw[8];
    #pragma unroll
    for (int j = 0; j < 8; j++) {
        int r = lr + 16 * j;
        aoff[j] = (uint32_t)(sh_asrc[r] * KDIM + ls * 8);
        boff[j] = (uint32_t)((n0 + r) * KDIM + ls * 8);
        dsw[j]  = sw_off(r, ls);
    }

    // prologue: issue chunk 0 into stage 0
    {
        uint32_t ab = sb;
        uint32_t bb = ab + 16384u;
        #pragma unroll
        for (int j = 0; j < 8; j++) {
            cp_async16(ab + dsw[j], Asrc + (size_t)aoff[j]);
            cp_async16(bb + dsw[j], Wb + (size_t)boff[j]);
        }
        CP_COMMIT();
    }

    // ---- fragment addressing: 4 warps (2x2), warp tile 64x64 ----
    int l = tid & 31;
    int w = tid >> 5;
    int mbase = (w >> 1) * 64;
    int nbase = (w & 1) * 64;
    int akey = l & 7;
    int ahib = l >> 4;
    uint32_t am128[4];
    #pragma unroll
    for (int mf = 0; mf < 4; mf++)
        am128[mf] = (uint32_t)((mbase + mf * 16 + (l & 15)) * 128);
    uint32_t bn128[8];
    #pragma unroll
    for (int nf = 0; nf < 8; nf++)
        bn128[nf] = (uint32_t)((nbase + nf * 8 + (l & 7)) * 128);
    uint32_t bq = (uint32_t)((l >> 3) & 3);

    float acc[4][8][4];
    #pragma unroll
    for (int i = 0; i < 4; i++)
        #pragma unroll
        for (int j = 0; j < 8; j++)
            #pragma unroll
            for (int k = 0; k < 4; k++) acc[i][j][k] = 0.0f;

    for (int c = 0; c < NCH; c++) {
        CP_WAIT0();          // chunk c's data (only outstanding group) complete
        __syncthreads();     // visibility of all threads' copies + stage (c-1) reads done

        if (c + 1 < NCH) {   // issue chunk c+1 into the stage chunk c-1 occupied
            uint32_t ab = sb + (uint32_t)((c + 1) & 1) * STAGE_BYTES;
            uint32_t bb = ab + 16384u;
            uint32_t ko = (uint32_t)(c + 1) * BK;
            #pragma unroll
            for (int j = 0; j < 8; j++) {
                cp_async16(ab + dsw[j], Asrc + (size_t)(aoff[j] + ko));
                cp_async16(bb + dsw[j], Wb + (size_t)(boff[j] + ko));
            }
            CP_COMMIT();
        }

        uint32_t ab = sb + (uint32_t)(c & 1) * STAGE_BYTES;
        uint32_t bb = ab + 16384u;
        #pragma unroll
        for (int p = 0; p < 2; p++) {
            uint32_t bf[8][4];
            #pragma unroll
            for (int nf = 0; nf < 8; nf++) {
                uint32_t slot = (((uint32_t)p << 2) | bq) ^ (uint32_t)akey;
                ldsm_x4(bf[nf], bb + bn128[nf] + (slot << 4));
            }
            #pragma unroll
            for (int sh = 0; sh < 2; sh++) {
                int s = 2 * p + sh;
                uint32_t af[4][4];
                #pragma unroll
                for (int mf = 0; mf < 4; mf++) {
                    uint32_t slot = (uint32_t)(((s << 1) | ahib) ^ akey);
                    ldsm_x4(af[mf], ab + am128[mf] + (slot << 4));
                }
                #pragma unroll
                for (int mf = 0; mf < 4; mf++)
                    #pragma unroll
                    for (int nf = 0; nf < 8; nf++)
                        mma_f16(acc[mf][nf], af[mf], &bf[nf][2 * sh]);
            }
        }
    }

    // ---- epilogue ----
    #pragma unroll
    for (int mf = 0; mf < 4; mf++) {
        int r0 = mbase + mf * 16 + (l >> 2);
        int r1 = r0 + 8;
        int a0 = sh_aidx[r0];
        int a1 = sh_aidx[r1];
        float w0 = GELU_EPI ? 1.0f : sh_wt[r0];
        float w1 = GELU_EPI ? 1.0f : sh_wt[r1];
        int t0 = a0 >> 1, t1 = a1 >> 1;
        #pragma unroll
        for (int nf = 0; nf < 8; nf++) {
            int cidx = nbase + nf * 8 + (l & 3) * 2;
            float b0c = sh_bias[cidx], b1c = sh_bias[cidx + 1];
            if (a0 >= 0) {
                float v0 = acc[mf][nf][0] + b0c;
                float v1 = acc[mf][nf][1] + b1c;
                if (GELU_EPI) {
                    __half2 hv = __floats2half2_rn(gelu_exact(v0), gelu_exact(v1));
                    *(__half2*)(g_H + (size_t)a0 * NOUT + n0 + cidx) = hv;
                } else {
                    float* o = out_final + (size_t)t0 * NOUT + n0 + cidx;
                    atomicAdd(o + 0, v0 * w0);
                    atomicAdd(o + 1, v1 * w0);
                }
            }
            if (a1 >= 0) {
                float v2 = acc[mf][nf][2] + b0c;
                float v3 = acc[mf][nf][3] + b1c;
                if (GELU_EPI) {
                    __half2 hv = __floats2half2_rn(gelu_exact(v2), gelu_exact(v3));
                    *(__half2*)(g_H + (size_t)a1 * NOUT + n0 + cidx) = hv;
                } else {
                    float* o = out_final + (size_t)t1 * NOUT + n0 + cidx;
                    atomicAdd(o + 0, v2 * w1);
                    atomicAdd(o + 1, v3 * w1);
                }
            }
        }
    }
}

// ---------------- launch ----------------
extern "C" void kernel_launch(void* const* d_in, const int* in_sizes, int n_in,
                              void* d_out, int out_size) {
    const float* x  = (const float*)d_in[0];
    const float* Wg = (const float*)d_in[1];
    const float* W1 = (const float*)d_in[2];
    const float* b1 = (const float*)d_in[3];
    const float* W2 = (const float*)d_in[4];
    const float* b2 = (const float*)d_in[5];
    float* out = (float*)d_out;
    int N = in_sizes[0] / D_DIM;   // 8192

    cudaFuncSetAttribute(moe_mma_kernel<D_DIM, H_DIM, true>,
                         cudaFuncAttributeMaxDynamicSharedMemorySize, SMEM_DYN);
    cudaFuncSetAttribute(moe_mma_kernel<H_DIM, D_DIM, false>,
                         cudaFuncAttributeMaxDynamicSharedMemorySize, SMEM_DYN);

    __half* w1c; cudaGetSymbolAddress((void**)&w1c, g_W1c);
    __half* w2c; cudaGetSymbolAddress((void**)&w2c, g_W2c);
    __half* xc;  cudaGetSymbolAddress((void**)&xc,  g_Xc);
    __half* hbuf; cudaGetSymbolAddress((void**)&hbuf, g_H);

    cudaMemsetAsync(out, 0, (size_t)out_size * sizeof(float));

    long long totjobs = 2LL * WN4 + XN4;
    int nblk = (int)((totjobs + 255) / 256);
    // 4th launch = GEMM2 so the profiler window lands on it
    prep_kernel<<<nblk, 256>>>((const float4*)W1, (const float4*)W2, (const float4*)x,
                               (__half2*)w1c, (__half2*)w2c, (__half2*)xc);
    gate_kernel<<<(N + 7) / 8, 256>>>(x, Wg, N);
    moe_mma_kernel<D_DIM, H_DIM, true >
        <<<dim3(H_DIM / BN, MAXA / BM, E_NUM), 128, SMEM_DYN>>>(xc, w1c, b1, nullptr);
    moe_mma_kernel<H_DIM, D_DIM, false>
        <<<dim3(D_DIM / BN, MAXA / BM, E_NUM), 128, SMEM_DYN>>>(hbuf, w2c, b2, out);
}

// round 15
// speedup vs baseline: 1.4745x; 1.4745x over previous
#include <cuda_runtime.h>
#include <cuda_fp16.h>
#include <math.h>
#include <cstdint>

// Problem constants
#define D_DIM 1024
#define H_DIM 4096
#define E_NUM 8
#define MAXA  16384
#define NTOK  8192
#define WN4   ((E_NUM * H_DIM * D_DIM) / 4)
#define XN4   ((NTOK * D_DIM) / 4)
#define MBLKS 24          // m-blocks per expert: covers cnt_e <= 3072 (>24 sigma margin)

// GEMM tiling (fp16: BK=64 = 128B rows); 256 threads, 8 warps (2x4), warp tile 64x32
#define BM 128
#define BN 128
#define BK 64
#define NSTAGE 3
#define STAGE_BYTES 32768
#define SMEM_DYN (NSTAGE * STAGE_BYTES + 2048)

// ---------------- device scratch ----------------
__device__ __half g_H[(size_t)MAXA * H_DIM];
__device__ __half g_W1c[(size_t)E_NUM * H_DIM * D_DIM];
__device__ __half g_W2c[(size_t)E_NUM * D_DIM * H_DIM];
__device__ __half g_Xc[(size_t)NTOK * D_DIM];
__device__ int    g_bucket[E_NUM * MAXA];
__device__ int    g_cnt[E_NUM];
__device__ float  g_wts[MAXA];

// ---------------- helpers ----------------
__device__ __forceinline__ uint32_t smem_u32(const void* p) {
    uint32_t a;
    asm("{ .reg .u64 t; cvta.to.shared.u64 t, %1; cvt.u32.u64 %0, t; }" : "=r"(a) : "l"(p));
    return a;
}
__device__ __forceinline__ float gelu_exact(float v) {
    return 0.5f * v * (1.0f + erff(v * 0.70710678118654752f));
}
__device__ __forceinline__ void mma_f16(float* d, const uint32_t* a, const uint32_t* b) {
    asm volatile(
        "mma.sync.aligned.m16n8k16.row.col.f32.f16.f16.f32 "
        "{%0,%1,%2,%3}, {%4,%5,%6,%7}, {%8,%9}, {%0,%1,%2,%3};"
        : "+f"(d[0]), "+f"(d[1]), "+f"(d[2]), "+f"(d[3])
        : "r"(a[0]), "r"(a[1]), "r"(a[2]), "r"(a[3]), "r"(b[0]), "r"(b[1]));
}
__device__ __forceinline__ void ldsm_x4(uint32_t* r, uint32_t addr) {
    asm volatile("ldmatrix.sync.aligned.m8n8.x4.shared.b16 {%0,%1,%2,%3}, [%4];"
                 : "=r"(r[0]), "=r"(r[1]), "=r"(r[2]), "=r"(r[3]) : "r"(addr));
}
__device__ __forceinline__ void cp_async16(uint32_t dst, const void* src) {
    asm volatile("cp.async.cg.shared.global [%0], [%1], 16;" :: "r"(dst), "l"(src));
}
#define CP_COMMIT() asm volatile("cp.async.commit_group;" ::: "memory")
#define CP_WAIT1()  asm volatile("cp.async.wait_group 1;" ::: "memory")

__device__ __forceinline__ uint32_t sw_off(int r, int s) {
    return (uint32_t)(r * 128 + ((s ^ (r & 7)) << 4));
}

// ---------------- one-shot prep: convert W1/W2/X to fp16, zero counters ----------------
__global__ void prep_kernel(const float4* __restrict__ W1,
                            const float4* __restrict__ W2,
                            const float4* __restrict__ X,
                            __half2* __restrict__ w1c,
                            __half2* __restrict__ w2c,
                            __half2* __restrict__ xc) {
    long long i = (long long)blockIdx.x * blockDim.x + threadIdx.x;
    if (i == 0) {
        #pragma unroll
        for (int e = 0; e < E_NUM; e++) g_cnt[e] = 0;
    }
    const float4* src;
    __half2* dst;
    long long j = i;
    if (i < WN4)                  { src = W1; dst = w1c; }
    else if (i < 2LL * WN4)       { src = W2; dst = w2c; j = i - WN4; }
    else if (i < 2LL * WN4 + XN4) { src = X;  dst = xc;  j = i - 2LL * WN4; }
    else return;
    float4 v = src[j];
    dst[2 * j + 0] = __floats2half2_rn(v.x, v.y);
    dst[2 * j + 1] = __floats2half2_rn(v.z, v.w);
}

// ---------------- gate ----------------
__global__ void gate_kernel(const float* __restrict__ x,
                            const float* __restrict__ Wg, int N) {
    int warp = (blockIdx.x * blockDim.x + threadIdx.x) >> 5;
    int lane = threadIdx.x & 31;
    if (warp >= N) return;
    const float* xr = x + (size_t)warp * D_DIM;
    float acc[E_NUM];
    #pragma unroll
    for (int e = 0; e < E_NUM; e++) acc[e] = 0.0f;
    for (int d = lane; d < D_DIM; d += 32) {
        float xv = xr[d];
        #pragma unroll
        for (int e = 0; e < E_NUM; e++) acc[e] += xv * Wg[e * D_DIM + d];
    }
    #pragma unroll
    for (int e = 0; e < E_NUM; e++)
        #pragma unroll
        for (int o = 16; o > 0; o >>= 1)
            acc[e] += __shfl_xor_sync(0xffffffffu, acc[e], o);
    if (lane == 0) {
        float m1 = -INFINITY, m2 = -INFINITY;
        int i1 = 0, i2 = 0;
        #pragma unroll
        for (int e = 0; e < E_NUM; e++) {
            float l = acc[e];
            if (l > m1)      { m2 = m1; i2 = i1; m1 = l; i1 = e; }
            else if (l > m2) { m2 = l; i2 = e; }
        }
        float e1 = expf(m2 - m1);
        float inv = 1.0f / (1.0f + e1);
        int a0 = warp * 2, a1 = warp * 2 + 1;
        g_wts[a0] = inv;
        g_wts[a1] = e1 * inv;
        int p0 = atomicAdd(&g_cnt[i1], 1);
        g_bucket[i1 * MAXA + p0] = a0;
        int p1 = atomicAdd(&g_cnt[i2], 1);
        g_bucket[i2 * MAXA + p1] = a1;
    }
}

// ---------------- fp16 mma.sync gathered GEMM, 64x32 warp tiles, 3-stage cp.async ----------------
// GELU_EPI=true : out -> g_H (fp16, rows = assignment)
// GELU_EPI=false: out -> atomicAdd into final output (rows = token = a>>1), *g_wts[a]
template <int KDIM, int NOUT, bool GELU_EPI>
__global__ __launch_bounds__(256, 2)
void moe_mma_kernel(const __half* __restrict__ Asrc,
                    const __half* __restrict__ W,
                    const float* __restrict__ bias,
                    float* __restrict__ out_final) {
    constexpr int NCH = KDIM / BK;

    extern __shared__ __align__(16) char dsm[];
    uint32_t sb = smem_u32(dsm);
    int*   sh_aidx = (int*)(dsm + NSTAGE * STAGE_BYTES);
    int*   sh_asrc = (int*)(dsm + NSTAGE * STAGE_BYTES + 512);
    float* sh_wt   = (float*)(dsm + NSTAGE * STAGE_BYTES + 1024);
    float* sh_bias = (float*)(dsm + NSTAGE * STAGE_BYTES + 1536);

    int e = blockIdx.z;
    int cnt = g_cnt[e];
    int m0 = blockIdx.y * BM;
    if (m0 >= cnt) return;
    int n0 = blockIdx.x * BN;
    int tid = threadIdx.x;

    if (tid < BM) {
        int mi = m0 + tid;
        int a = (mi < cnt) ? g_bucket[e * MAXA + mi] : -1;
        sh_aidx[tid] = a;
        sh_asrc[tid] = (a >= 0) ? (GELU_EPI ? (a >> 1) : a) : 0;
        sh_wt[tid]   = (!GELU_EPI && a >= 0) ? g_wts[a] : 0.0f;
    } else {
        int c = tid - BM;
        sh_bias[c] = bias[(size_t)e * NOUT + n0 + c];
    }
    __syncthreads();

    const __half* Wb = W + (size_t)e * NOUT * KDIM;

    // ---- loader mapping: slot = tid&7 (8 fp16 each), rows = (tid>>3) + 32j ----
    int ls = tid & 7;
    int lr = tid >> 3;
    uint32_t aoff[4], boff[4], dsw[4];
    #pragma unroll
    for (int j = 0; j < 4; j++) {
        int r = lr + 32 * j;
        aoff[j] = (uint32_t)(sh_asrc[r] * KDIM + ls * 8);
        boff[j] = (uint32_t)((n0 + r) * KDIM + ls * 8);
        dsw[j]  = sw_off(r, ls);
    }

    // prologue: fill stages 0..NSTAGE-2
    #pragma unroll
    for (int c = 0; c < NSTAGE - 1; c++) {
        uint32_t ab = sb + (uint32_t)c * STAGE_BYTES;
        uint32_t bb = ab + 16384u;
        uint32_t ko = (uint32_t)c * BK;
        #pragma unroll
        for (int j = 0; j < 4; j++) {
            cp_async16(ab + dsw[j], Asrc + (size_t)(aoff[j] + ko));
            cp_async16(bb + dsw[j], Wb + (size_t)(boff[j] + ko));
        }
        CP_COMMIT();
    }

    // ---- fragment addressing: 8 warps (2x4), warp tile 64x32 ----
    int l = tid & 31;
    int w = tid >> 5;
    int mbase = (w >> 2) * 64;
    int nbase = (w & 3) * 32;
    int akey = l & 7;
    int ahib = l >> 4;
    uint32_t am128[4];
    #pragma unroll
    for (int mf = 0; mf < 4; mf++)
        am128[mf] = (uint32_t)((mbase + mf * 16 + (l & 15)) * 128);
    uint32_t bn128[4];
    #pragma unroll
    for (int nf = 0; nf < 4; nf++)
        bn128[nf] = (uint32_t)((nbase + nf * 8 + (l & 7)) * 128);
    uint32_t bq = (uint32_t)((l >> 3) & 3);

    float acc[4][4][4];
    #pragma unroll
    for (int i = 0; i < 4; i++)
        #pragma unroll
        for (int j = 0; j < 4; j++)
            #pragma unroll
            for (int k = 0; k < 4; k++) acc[i][j][k] = 0.0f;

    for (int c = 0; c < NCH; c++) {
        CP_WAIT1();
        __syncthreads();

        if (c + NSTAGE - 1 < NCH) {
            int cn = c + NSTAGE - 1;
            uint32_t ab = sb + (uint32_t)(cn % NSTAGE) * STAGE_BYTES;
            uint32_t bb = ab + 16384u;
            uint32_t ko = (uint32_t)cn * BK;
            #pragma unroll
            for (int j = 0; j < 4; j++) {
                cp_async16(ab + dsw[j], Asrc + (size_t)(aoff[j] + ko));
                cp_async16(bb + dsw[j], Wb + (size_t)(boff[j] + ko));
            }
        }
        CP_COMMIT();

        uint32_t ab = sb + (uint32_t)(c % NSTAGE) * STAGE_BYTES;
        uint32_t bb = ab + 16384u;
        #pragma unroll
        for (int p = 0; p < 2; p++) {
            uint32_t bf[4][4];
            #pragma unroll
            for (int nf = 0; nf < 4; nf++) {
                uint32_t slot = (((uint32_t)p << 2) | bq) ^ (uint32_t)akey;
                ldsm_x4(bf[nf], bb + bn128[nf] + (slot << 4));
            }
            #pragma unroll
            for (int sh = 0; sh < 2; sh++) {
                int s = 2 * p + sh;
                uint32_t af[4][4];
                #pragma unroll
                for (int mf = 0; mf < 4; mf++) {
                    uint32_t slot = (uint32_t)(((s << 1) | ahib) ^ akey);
                    ldsm_x4(af[mf], ab + am128[mf] + (slot << 4));
                }
                #pragma unroll
                for (int mf = 0; mf < 4; mf++)
                    #pragma unroll
                    for (int nf = 0; nf < 4; nf++)
                        mma_f16(acc[mf][nf], af[mf], &bf[nf][2 * sh]);
            }
        }
    }

    // ---- epilogue ----
    #pragma unroll
    for (int mf = 0; mf < 4; mf++) {
        int r0 = mbase + mf * 16 + (l >> 2);
        int r1 = r0 + 8;
        int a0 = sh_aidx[r0];
        int a1 = sh_aidx[r1];
        float w0 = GELU_EPI ? 1.0f : sh_wt[r0];
        float w1 = GELU_EPI ? 1.0f : sh_wt[r1];
        int t0 = a0 >> 1, t1 = a1 >> 1;
        #pragma unroll
        for (int nf = 0; nf < 4; nf++) {
            int cidx = nbase + nf * 8 + (l & 3) * 2;
            float b0c = sh_bias[cidx], b1c = sh_bias[cidx + 1];
            if (a0 >= 0) {
                float v0 = acc[mf][nf][0] + b0c;
                float v1 = acc[mf][nf][1] + b1c;
                if (GELU_EPI) {
                    __half2 hv = __floats2half2_rn(gelu_exact(v0), gelu_exact(v1));
                    *(__half2*)(g_H + (size_t)a0 * NOUT + n0 + cidx) = hv;
                } else {
                    float* o = out_final + (size_t)t0 * NOUT + n0 + cidx;
                    atomicAdd(o + 0, v0 * w0);
                    atomicAdd(o + 1, v1 * w0);
                }
            }
            if (a1 >= 0) {
                float v2 = acc[mf][nf][2] + b0c;
                float v3 = acc[mf][nf][3] + b1c;
                if (GELU_EPI) {
                    __half2 hv = __floats2half2_rn(gelu_exact(v2), gelu_exact(v3));
                    *(__half2*)(g_H + (size_t)a1 * NOUT + n0 + cidx) = hv;
                } else {
                    float* o = out_final + (size_t)t1 * NOUT + n0 + cidx;
                    atomicAdd(o + 0, v2 * w1);
                    atomicAdd(o + 1, v3 * w1);
                }
            }
        }
    }
}

// ---------------- launch ----------------
extern "C" void kernel_launch(void* const* d_in, const int* in_sizes, int n_in,
                              void* d_out, int out_size) {
    const float* x  = (const float*)d_in[0];
    const float* Wg = (const float*)d_in[1];
    const float* W1 = (const float*)d_in[2];
    const float* b1 = (const float*)d_in[3];
    const float* W2 = (const float*)d_in[4];
    const float* b2 = (const float*)d_in[5];
    float* out = (float*)d_out;
    int N = in_sizes[0] / D_DIM;   // 8192

    cudaFuncSetAttribute(moe_mma_kernel<D_DIM, H_DIM, true>,
                         cudaFuncAttributeMaxDynamicSharedMemorySize, SMEM_DYN);
    cudaFuncSetAttribute(moe_mma_kernel<H_DIM, D_DIM, false>,
                         cudaFuncAttributeMaxDynamicSharedMemorySize, SMEM_DYN);

    __half* w1c; cudaGetSymbolAddress((void**)&w1c, g_W1c);
    __half* w2c; cudaGetSymbolAddress((void**)&w2c, g_W2c);
    __half* xc;  cudaGetSymbolAddress((void**)&xc,  g_Xc);
    __half* hbuf; cudaGetSymbolAddress((void**)&hbuf, g_H);

    cudaMemsetAsync(out, 0, (size_t)out_size * sizeof(float));

    long long totjobs = 2LL * WN4 + XN4;
    int nblk = (int)((totjobs + 255) / 256);
    // 4th kernel launch = GEMM2 so the profiler window lands on it
    prep_kernel<<<nblk, 256>>>((const float4*)W1, (const float4*)W2, (const float4*)x,
                               (__half2*)w1c, (__half2*)w2c, (__half2*)xc);
    gate_kernel<<<(N + 7) / 8, 256>>>(x, Wg, N);
    moe_mma_kernel<D_DIM, H_DIM, true >
        <<<dim3(H_DIM / BN, MBLKS, E_NUM), 256, SMEM_DYN>>>(xc, w1c, b1, nullptr);
    moe_mma_kernel<H_DIM, D_DIM, false>
        <<<dim3(D_DIM / BN, MBLKS, E_NUM), 256, SMEM_DYN>>>(hbuf, w2c, b2, out);
}

// round 16
// speedup vs baseline: 1.4847x; 1.0069x over previous
#include <cuda_runtime.h>
#include <cuda_fp16.h>
#include <math.h>
#include <cstdint>

// Problem constants
#define D_DIM 1024
#define H_DIM 4096
#define E_NUM 8
#define MAXA  16384
#define NTOK  8192
#define WN4   ((E_NUM * H_DIM * D_DIM) / 4)
#define XN4   ((NTOK * D_DIM) / 4)
#define MBLKS 24          // m-blocks per expert: covers cnt_e <= 3072 (>24 sigma margin)

// GEMM tiling (fp16: BK=64 = 128B rows); 256 threads, 8 warps (2x4), warp tile 64x32
#define BM 128
#define BN 128
#define BK 64
#define NSTAGE 3
#define STAGE_BYTES 32768
#define SMEM_DYN (NSTAGE * STAGE_BYTES + 2048)

// ---------------- device scratch ----------------
__device__ __half g_H[(size_t)MAXA * H_DIM];
__device__ __half g_W1c[(size_t)E_NUM * H_DIM * D_DIM];
__device__ __half g_W2c[(size_t)E_NUM * D_DIM * H_DIM];
__device__ __half g_Xc[(size_t)NTOK * D_DIM];
__device__ int    g_bucket[E_NUM * MAXA];
__device__ int    g_cnt[E_NUM];
__device__ float  g_wts[MAXA];

// ---------------- helpers ----------------
__device__ __forceinline__ uint32_t smem_u32(const void* p) {
    uint32_t a;
    asm("{ .reg .u64 t; cvta.to.shared.u64 t, %1; cvt.u32.u64 %0, t; }" : "=r"(a) : "l"(p));
    return a;
}
__device__ __forceinline__ float gelu_exact(float v) {
    return 0.5f * v * (1.0f + erff(v * 0.70710678118654752f));
}
__device__ __forceinline__ void mma_f16(float* d, const uint32_t* a, const uint32_t* b) {
    asm volatile(
        "mma.sync.aligned.m16n8k16.row.col.f32.f16.f16.f32 "
        "{%0,%1,%2,%3}, {%4,%5,%6,%7}, {%8,%9}, {%0,%1,%2,%3};"
        : "+f"(d[0]), "+f"(d[1]), "+f"(d[2]), "+f"(d[3])
        : "r"(a[0]), "r"(a[1]), "r"(a[2]), "r"(a[3]), "r"(b[0]), "r"(b[1]));
}
__device__ __forceinline__ void ldsm_x4(uint32_t* r, uint32_t addr) {
    asm volatile("ldmatrix.sync.aligned.m8n8.x4.shared.b16 {%0,%1,%2,%3}, [%4];"
                 : "=r"(r[0]), "=r"(r[1]), "=r"(r[2]), "=r"(r[3]) : "r"(addr));
}
__device__ __forceinline__ void cp_async16(uint32_t dst, const void* src) {
    asm volatile("cp.async.cg.shared.global [%0], [%1], 16;" :: "r"(dst), "l"(src));
}
#define CP_COMMIT() asm volatile("cp.async.commit_group;" ::: "memory")
#define CP_WAIT1()  asm volatile("cp.async.wait_group 1;" ::: "memory")

__device__ __forceinline__ uint32_t sw_off(int r, int s) {
    return (uint32_t)(r * 128 + ((s ^ (r & 7)) << 4));
}

// ---------------- prep kernels: fp32 -> fp16(rn) ----------------
__global__ void prep_xw1_kernel(const float4* __restrict__ W1,
                                const float4* __restrict__ X,
                                __half2* __restrict__ w1c,
                                __half2* __restrict__ xc) {
    long long i = (long long)blockIdx.x * blockDim.x + threadIdx.x;
    const float4* src;
    __half2* dst;
    long long j = i;
    if (i < WN4)                  { src = W1; dst = w1c; }
    else if (i < (long long)WN4 + XN4) { src = X; dst = xc; j = i - WN4; }
    else return;
    float4 v = src[j];
    dst[2 * j + 0] = __floats2half2_rn(v.x, v.y);
    dst[2 * j + 1] = __floats2half2_rn(v.z, v.w);
}

__global__ void prep_w2_kernel(const float4* __restrict__ W2,
                               __half2* __restrict__ w2c) {
    long long i = (long long)blockIdx.x * blockDim.x + threadIdx.x;
    if (i >= WN4) return;
    float4 v = W2[i];
    w2c[2 * i + 0] = __floats2half2_rn(v.x, v.y);
    w2c[2 * i + 1] = __floats2half2_rn(v.z, v.w);
}

// ---------------- gate ----------------
__global__ void gate_kernel(const float* __restrict__ x,
                            const float* __restrict__ Wg, int N) {
    int warp = (blockIdx.x * blockDim.x + threadIdx.x) >> 5;
    int lane = threadIdx.x & 31;
    if (warp >= N) return;
    const float* xr = x + (size_t)warp * D_DIM;
    float acc[E_NUM];
    #pragma unroll
    for (int e = 0; e < E_NUM; e++) acc[e] = 0.0f;
    for (int d = lane; d < D_DIM; d += 32) {
        float xv = xr[d];
        #pragma unroll
        for (int e = 0; e < E_NUM; e++) acc[e] += xv * Wg[e * D_DIM + d];
    }
    #pragma unroll
    for (int e = 0; e < E_NUM; e++)
        #pragma unroll
        for (int o = 16; o > 0; o >>= 1)
            acc[e] += __shfl_xor_sync(0xffffffffu, acc[e], o);
    if (lane == 0) {
        float m1 = -INFINITY, m2 = -INFINITY;
        int i1 = 0, i2 = 0;
        #pragma unroll
        for (int e = 0; e < E_NUM; e++) {
            float l = acc[e];
            if (l > m1)      { m2 = m1; i2 = i1; m1 = l; i1 = e; }
            else if (l > m2) { m2 = l; i2 = e; }
        }
        float e1 = expf(m2 - m1);
        float inv = 1.0f / (1.0f + e1);
        int a0 = warp * 2, a1 = warp * 2 + 1;
        g_wts[a0] = inv;
        g_wts[a1] = e1 * inv;
        int p0 = atomicAdd(&g_cnt[i1], 1);
        g_bucket[i1 * MAXA + p0] = a0;
        int p1 = atomicAdd(&g_cnt[i2], 1);
        g_bucket[i2 * MAXA + p1] = a1;
    }
}

// ---------------- fp16 mma.sync gathered GEMM, 64x32 warp tiles, 3-stage cp.async ----------------
template <int KDIM, int NOUT, bool GELU_EPI>
__global__ __launch_bounds__(256, 2)
void moe_mma_kernel(const __half* __restrict__ Asrc,
                    const __half* __restrict__ W,
                    const float* __restrict__ bias,
                    float* __restrict__ out_final) {
    constexpr int NCH = KDIM / BK;

    extern __shared__ __align__(16) char dsm[];
    uint32_t sb = smem_u32(dsm);
    int*   sh_aidx = (int*)(dsm + NSTAGE * STAGE_BYTES);
    int*   sh_asrc = (int*)(dsm + NSTAGE * STAGE_BYTES + 512);
    float* sh_wt   = (float*)(dsm + NSTAGE * STAGE_BYTES + 1024);
    float* sh_bias = (float*)(dsm + NSTAGE * STAGE_BYTES + 1536);

    int e = blockIdx.z;
    int cnt = g_cnt[e];
    int m0 = blockIdx.y * BM;
    if (m0 >= cnt) return;
    int n0 = blockIdx.x * BN;
    int tid = threadIdx.x;

    if (tid < BM) {
        int mi = m0 + tid;
        int a = (mi < cnt) ? g_bucket[e * MAXA + mi] : -1;
        sh_aidx[tid] = a;
        sh_asrc[tid] = (a >= 0) ? (GELU_EPI ? (a >> 1) : a) : 0;
        sh_wt[tid]   = (!GELU_EPI && a >= 0) ? g_wts[a] : 0.0f;
    } else {
        int c = tid - BM;
        sh_bias[c] = bias[(size_t)e * NOUT + n0 + c];
    }
    __syncthreads();

    const __half* Wb = W + (size_t)e * NOUT * KDIM;

    int ls = tid & 7;
    int lr = tid >> 3;
    uint32_t aoff[4], boff[4], dsw[4];
    #pragma unroll
    for (int j = 0; j < 4; j++) {
        int r = lr + 32 * j;
        aoff[j] = (uint32_t)(sh_asrc[r] * KDIM + ls * 8);
        boff[j] = (uint32_t)((n0 + r) * KDIM + ls * 8);
        dsw[j]  = sw_off(r, ls);
    }

    #pragma unroll
    for (int c = 0; c < NSTAGE - 1; c++) {
        uint32_t ab = sb + (uint32_t)c * STAGE_BYTES;
        uint32_t bb = ab + 16384u;
        uint32_t ko = (uint32_t)c * BK;
        #pragma unroll
        for (int j = 0; j < 4; j++) {
            cp_async16(ab + dsw[j], Asrc + (size_t)(aoff[j] + ko));
            cp_async16(bb + dsw[j], Wb + (size_t)(boff[j] + ko));
        }
        CP_COMMIT();
    }

    int l = tid & 31;
    int w = tid >> 5;
    int mbase = (w >> 2) * 64;
    int nbase = (w & 3) * 32;
    int akey = l & 7;
    int ahib = l >> 4;
    uint32_t am128[4];
    #pragma unroll
    for (int mf = 0; mf < 4; mf++)
        am128[mf] = (uint32_t)((mbase + mf * 16 + (l & 15)) * 128);
    uint32_t bn128[4];
    #pragma unroll
    for (int nf = 0; nf < 4; nf++)
        bn128[nf] = (uint32_t)((nbase + nf * 8 + (l & 7)) * 128);
    uint32_t bq = (uint32_t)((l >> 3) & 3);

    float acc[4][4][4];
    #pragma unroll
    for (int i = 0; i < 4; i++)
        #pragma unroll
        for (int j = 0; j < 4; j++)
            #pragma unroll
            for (int k = 0; k < 4; k++) acc[i][j][k] = 0.0f;

    for (int c = 0; c < NCH; c++) {
        CP_WAIT1();
        __syncthreads();

        if (c + NSTAGE - 1 < NCH) {
            int cn = c + NSTAGE - 1;
            uint32_t ab = sb + (uint32_t)(cn % NSTAGE) * STAGE_BYTES;
            uint32_t bb = ab + 16384u;
            uint32_t ko = (uint32_t)cn * BK;
            #pragma unroll
            for (int j = 0; j < 4; j++) {
                cp_async16(ab + dsw[j], Asrc + (size_t)(aoff[j] + ko));
                cp_async16(bb + dsw[j], Wb + (size_t)(boff[j] + ko));
            }
        }
        CP_COMMIT();

        uint32_t ab = sb + (uint32_t)(c % NSTAGE) * STAGE_BYTES;
        uint32_t bb = ab + 16384u;
        #pragma unroll
        for (int p = 0; p < 2; p++) {
            uint32_t bf[4][4];
            #pragma unroll
            for (int nf = 0; nf < 4; nf++) {
                uint32_t slot = (((uint32_t)p << 2) | bq) ^ (uint32_t)akey;
                ldsm_x4(bf[nf], bb + bn128[nf] + (slot << 4));
            }
            #pragma unroll
            for (int sh = 0; sh < 2; sh++) {
                int s = 2 * p + sh;
                uint32_t af[4][4];
                #pragma unroll
                for (int mf = 0; mf < 4; mf++) {
                    uint32_t slot = (uint32_t)(((s << 1) | ahib) ^ akey);
                    ldsm_x4(af[mf], ab + am128[mf] + (slot << 4));
                }
                #pragma unroll
                for (int mf = 0; mf < 4; mf++)
                    #pragma unroll
                    for (int nf = 0; nf < 4; nf++)
                        mma_f16(acc[mf][nf], af[mf], &bf[nf][2 * sh]);
            }
        }
    }

    // ---- epilogue ----
    #pragma unroll
    for (int mf = 0; mf < 4; mf++) {
        int r0 = mbase + mf * 16 + (l >> 2);
        int r1 = r0 + 8;
        int a0 = sh_aidx[r0];
        int a1 = sh_aidx[r1];
        float w0 = GELU_EPI ? 1.0f : sh_wt[r0];
        float w1 = GELU_EPI ? 1.0f : sh_wt[r1];
        int t0 = a0 >> 1, t1 = a1 >> 1;
        #pragma unroll
        for (int nf = 0; nf < 4; nf++) {
            int cidx = nbase + nf * 8 + (l & 3) * 2;
            float b0c = sh_bias[cidx], b1c = sh_bias[cidx + 1];
            if (a0 >= 0) {
                float v0 = acc[mf][nf][0] + b0c;
                float v1 = acc[mf][nf][1] + b1c;
                if (GELU_EPI) {
                    __half2 hv = __floats2half2_rn(gelu_exact(v0), gelu_exact(v1));
                    *(__half2*)(g_H + (size_t)a0 * NOUT + n0 + cidx) = hv;
                } else {
                    float* o = out_final + (size_t)t0 * NOUT + n0 + cidx;
                    atomicAdd(o + 0, v0 * w0);
                    atomicAdd(o + 1, v1 * w0);
                }
            }
            if (a1 >= 0) {
                float v2 = acc[mf][nf][2] + b0c;
                float v3 = acc[mf][nf][3] + b1c;
                if (GELU_EPI) {
                    __half2 hv = __floats2half2_rn(gelu_exact(v2), gelu_exact(v3));
                    *(__half2*)(g_H + (size_t)a1 * NOUT + n0 + cidx) = hv;
                } else {
                    float* o = out_final + (size_t)t1 * NOUT + n0 + cidx;
                    atomicAdd(o + 0, v2 * w1);
                    atomicAdd(o + 1, v3 * w1);
                }
            }
        }
    }
}

// ---------------- streams/events for capture fork-join (created once at load) ----------------
static cudaStream_t s_prep = nullptr;   // prep_w2 + memset(out)
static cudaStream_t s_gate = nullptr;   // zero counters + gate
static cudaEvent_t  ev_fork = nullptr, ev_prep = nullptr, ev_gate = nullptr;
static struct StreamInit {
    StreamInit() {
        cudaStreamCreateWithFlags(&s_prep, cudaStreamNonBlocking);
        cudaStreamCreateWithFlags(&s_gate, cudaStreamNonBlocking);
        cudaEventCreateWithFlags(&ev_fork, cudaEventDisableTiming);
        cudaEventCreateWithFlags(&ev_prep, cudaEventDisableTiming);
        cudaEventCreateWithFlags(&ev_gate, cudaEventDisableTiming);
    }
} s_init;

// ---------------- launch ----------------
extern "C" void kernel_launch(void* const* d_in, const int* in_sizes, int n_in,
                              void* d_out, int out_size) {
    const float* x  = (const float*)d_in[0];
    const float* Wg = (const float*)d_in[1];
    const float* W1 = (const float*)d_in[2];
    const float* b1 = (const float*)d_in[3];
    const float* W2 = (const float*)d_in[4];
    const float* b2 = (const float*)d_in[5];
    float* out = (float*)d_out;
    int N = in_sizes[0] / D_DIM;   // 8192

    cudaFuncSetAttribute(moe_mma_kernel<D_DIM, H_DIM, true>,
                         cudaFuncAttributeMaxDynamicSharedMemorySize, SMEM_DYN);
    cudaFuncSetAttribute(moe_mma_kernel<H_DIM, D_DIM, false>,
                         cudaFuncAttributeMaxDynamicSharedMemorySize, SMEM_DYN);

    __half* w1c; cudaGetSymbolAddress((void**)&w1c, g_W1c);
    __half* w2c; cudaGetSymbolAddress((void**)&w2c, g_W2c);
    __half* xc;  cudaGetSymbolAddress((void**)&xc,  g_Xc);
    __half* hbuf; cudaGetSymbolAddress((void**)&hbuf, g_H);
    int* cntp;  cudaGetSymbolAddress((void**)&cntp, g_cnt);

    // ---- fork ----
    cudaEventRecord(ev_fork, 0);
    cudaStreamWaitEvent(s_prep, ev_fork, 0);
    cudaStreamWaitEvent(s_gate, ev_fork, 0);

    // side stream A: W2 conversion + output zeroing (needed only by GEMM2)
    {
        int nblk = (int)(((long long)WN4 + 255) / 256);
        prep_w2_kernel<<<nblk, 256, 0, s_prep>>>((const float4*)W2, (__half2*)w2c);
        cudaMemsetAsync(out, 0, (size_t)out_size * sizeof(float), s_prep);
        cudaEventRecord(ev_prep, s_prep);
    }

    // side stream B: routing (zero counters, then gate) — needs only fp32 x, Wg
    {
        cudaMemsetAsync(cntp, 0, E_NUM * sizeof(int), s_gate);
        gate_kernel<<<(N + 7) / 8, 256, 0, s_gate>>>(x, Wg, N);
        cudaEventRecord(ev_gate, s_gate);
    }

    // main stream: X+W1 conversion (GEMM1 inputs)
    {
        long long jobs = (long long)WN4 + XN4;
        int nblk = (int)((jobs + 255) / 256);
        prep_xw1_kernel<<<nblk, 256>>>((const float4*)W1, (const float4*)x,
                                       (__half2*)w1c, (__half2*)xc);
    }

    // join routing before GEMM1 (runs concurrent with prep_w2 on s_prep)
    cudaStreamWaitEvent(0, ev_gate, 0);
    moe_mma_kernel<D_DIM, H_DIM, true >
        <<<dim3(H_DIM / BN, MBLKS, E_NUM), 256, SMEM_DYN>>>(xc, w1c, b1, nullptr);

    // join W2 conversion + out zeroing before GEMM2
    cudaStreamWaitEvent(0, ev_prep, 0);
    moe_mma_kernel<H_DIM, D_DIM, false>
        <<<dim3(D_DIM / BN, MBLKS, E_NUM), 256, SMEM_DYN>>>(hbuf, w2c, b2, out);
}

// round 17
// speedup vs baseline: 1.4928x; 1.0055x over previous
#include <cuda_runtime.h>
#include <cuda_fp16.h>
#include <math.h>
#include <cstdint>

// Problem constants
#define D_DIM 1024
#define H_DIM 4096
#define E_NUM 8
#define MAXA  16384
#define NTOK  8192
#define WN4   ((E_NUM * H_DIM * D_DIM) / 4)
#define XN4   ((NTOK * D_DIM) / 4)
#define MBLKS 24          // m-blocks per expert: covers cnt_e <= 3072 (>24 sigma margin)

// GEMM tiling (fp16: BK=64 = 128B rows); 256 threads, 8 warps (2x4), warp tile 64x32
#define BM 128
#define BN 128
#define BK 64
#define NSTAGE 3
#define STAGE_BYTES 32768
#define SMEM_DYN (NSTAGE * STAGE_BYTES + 2048)

// ---------------- device scratch ----------------
__device__ __half g_H[(size_t)MAXA * H_DIM];
__device__ __half g_W1c[(size_t)E_NUM * H_DIM * D_DIM];
__device__ __half g_W2c[(size_t)E_NUM * D_DIM * H_DIM];
__device__ __half g_Xc[(size_t)NTOK * D_DIM];
__device__ int    g_bucket[E_NUM * MAXA];
__device__ int    g_cnt[E_NUM];
__device__ float  g_wts[MAXA];

// ---------------- helpers ----------------
__device__ __forceinline__ uint32_t smem_u32(const void* p) {
    uint32_t a;
    asm("{ .reg .u64 t; cvta.to.shared.u64 t, %1; cvt.u32.u64 %0, t; }" : "=r"(a) : "l"(p));
    return a;
}
__device__ __forceinline__ float gelu_exact(float v) {
    return 0.5f * v * (1.0f + erff(v * 0.70710678118654752f));
}
__device__ __forceinline__ void red_add_v2(float* p, float v0, float v1) {
    asm volatile("red.global.add.v2.f32 [%0], {%1, %2};"
                 :: "l"(p), "f"(v0), "f"(v1) : "memory");
}
__device__ __forceinline__ void mma_f16(float* d, const uint32_t* a, const uint32_t* b) {
    asm volatile(
        "mma.sync.aligned.m16n8k16.row.col.f32.f16.f16.f32 "
        "{%0,%1,%2,%3}, {%4,%5,%6,%7}, {%8,%9}, {%0,%1,%2,%3};"
        : "+f"(d[0]), "+f"(d[1]), "+f"(d[2]), "+f"(d[3])
        : "r"(a[0]), "r"(a[1]), "r"(a[2]), "r"(a[3]), "r"(b[0]), "r"(b[1]));
}
__device__ __forceinline__ void ldsm_x4(uint32_t* r, uint32_t addr) {
    asm volatile("ldmatrix.sync.aligned.m8n8.x4.shared.b16 {%0,%1,%2,%3}, [%4];"
                 : "=r"(r[0]), "=r"(r[1]), "=r"(r[2]), "=r"(r[3]) : "r"(addr));
}
__device__ __forceinline__ void cp_async16(uint32_t dst, const void* src) {
    asm volatile("cp.async.cg.shared.global [%0], [%1], 16;" :: "r"(dst), "l"(src));
}
#define CP_COMMIT() asm volatile("cp.async.commit_group;" ::: "memory")
#define CP_WAIT1()  asm volatile("cp.async.wait_group 1;" ::: "memory")

__device__ __forceinline__ uint32_t sw_off(int r, int s) {
    return (uint32_t)(r * 128 + ((s ^ (r & 7)) << 4));
}

// ---------------- prep kernels: fp32 -> fp16(rn) ----------------
__global__ void prep_xw1_kernel(const float4* __restrict__ W1,
                                const float4* __restrict__ X,
                                __half2* __restrict__ w1c,
                                __half2* __restrict__ xc) {
    long long i = (long long)blockIdx.x * blockDim.x + threadIdx.x;
    const float4* src;
    __half2* dst;
    long long j = i;
    if (i < WN4)                  { src = W1; dst = w1c; }
    else if (i < (long long)WN4 + XN4) { src = X; dst = xc; j = i - WN4; }
    else return;
    float4 v = src[j];
    dst[2 * j + 0] = __floats2half2_rn(v.x, v.y);
    dst[2 * j + 1] = __floats2half2_rn(v.z, v.w);
}

__global__ void prep_w2_kernel(const float4* __restrict__ W2,
                               __half2* __restrict__ w2c) {
    long long i = (long long)blockIdx.x * blockDim.x + threadIdx.x;
    if (i >= WN4) return;
    float4 v = W2[i];
    w2c[2 * i + 0] = __floats2half2_rn(v.x, v.y);
    w2c[2 * i + 1] = __floats2half2_rn(v.z, v.w);
}

// ---------------- gate ----------------
__global__ void gate_kernel(const float* __restrict__ x,
                            const float* __restrict__ Wg, int N) {
    int warp = (blockIdx.x * blockDim.x + threadIdx.x) >> 5;
    int lane = threadIdx.x & 31;
    if (warp >= N) return;
    const float* xr = x + (size_t)warp * D_DIM;
    float acc[E_NUM];
    #pragma unroll
    for (int e = 0; e < E_NUM; e++) acc[e] = 0.0f;
    for (int d = lane; d < D_DIM; d += 32) {
        float xv = xr[d];
        #pragma unroll
        for (int e = 0; e < E_NUM; e++) acc[e] += xv * Wg[e * D_DIM + d];
    }
    #pragma unroll
    for (int e = 0; e < E_NUM; e++)
        #pragma unroll
        for (int o = 16; o > 0; o >>= 1)
            acc[e] += __shfl_xor_sync(0xffffffffu, acc[e], o);
    if (lane == 0) {
        float m1 = -INFINITY, m2 = -INFINITY;
        int i1 = 0, i2 = 0;
        #pragma unroll
        for (int e = 0; e < E_NUM; e++) {
            float l = acc[e];
            if (l > m1)      { m2 = m1; i2 = i1; m1 = l; i1 = e; }
            else if (l > m2) { m2 = l; i2 = e; }
        }
        float e1 = expf(m2 - m1);
        float inv = 1.0f / (1.0f + e1);
        int a0 = warp * 2, a1 = warp * 2 + 1;
        g_wts[a0] = inv;
        g_wts[a1] = e1 * inv;
        int p0 = atomicAdd(&g_cnt[i1], 1);
        g_bucket[i1 * MAXA + p0] = a0;
        int p1 = atomicAdd(&g_cnt[i2], 1);
        g_bucket[i2 * MAXA + p1] = a1;
    }
}

// ---------------- fp16 mma.sync gathered GEMM, 64x32 warp tiles, 3-stage cp.async ----------------
template <int KDIM, int NOUT, bool GELU_EPI>
__global__ __launch_bounds__(256, 2)
void moe_mma_kernel(const __half* __restrict__ Asrc,
                    const __half* __restrict__ W,
                    const float* __restrict__ bias,
                    float* __restrict__ out_final) {
    constexpr int NCH = KDIM / BK;

    extern __shared__ __align__(16) char dsm[];
    uint32_t sb = smem_u32(dsm);
    int*   sh_aidx = (int*)(dsm + NSTAGE * STAGE_BYTES);
    int*   sh_asrc = (int*)(dsm + NSTAGE * STAGE_BYTES + 512);
    float* sh_wt   = (float*)(dsm + NSTAGE * STAGE_BYTES + 1024);
    float* sh_bias = (float*)(dsm + NSTAGE * STAGE_BYTES + 1536);

    int e = blockIdx.z;
    int cnt = g_cnt[e];
    int m0 = blockIdx.y * BM;
    if (m0 >= cnt) return;
    int n0 = blockIdx.x * BN;
    int tid = threadIdx.x;

    if (tid < BM) {
        int mi = m0 + tid;
        int a = (mi < cnt) ? g_bucket[e * MAXA + mi] : -1;
        sh_aidx[tid] = a;
        sh_asrc[tid] = (a >= 0) ? (GELU_EPI ? (a >> 1) : a) : 0;
        sh_wt[tid]   = (!GELU_EPI && a >= 0) ? g_wts[a] : 0.0f;
    } else {
        int c = tid - BM;
        sh_bias[c] = bias[(size_t)e * NOUT + n0 + c];
    }
    __syncthreads();

    const __half* Wb = W + (size_t)e * NOUT * KDIM;

    int ls = tid & 7;
    int lr = tid >> 3;
    uint32_t aoff[4], boff[4], dsw[4];
    #pragma unroll
    for (int j = 0; j < 4; j++) {
        int r = lr + 32 * j;
        aoff[j] = (uint32_t)(sh_asrc[r] * KDIM + ls * 8);
        boff[j] = (uint32_t)((n0 + r) * KDIM + ls * 8);
        dsw[j]  = sw_off(r, ls);
    }

    #pragma unroll
    for (int c = 0; c < NSTAGE - 1; c++) {
        uint32_t ab = sb + (uint32_t)c * STAGE_BYTES;
        uint32_t bb = ab + 16384u;
        uint32_t ko = (uint32_t)c * BK;
        #pragma unroll
        for (int j = 0; j < 4; j++) {
            cp_async16(ab + dsw[j], Asrc + (size_t)(aoff[j] + ko));
            cp_async16(bb + dsw[j], Wb + (size_t)(boff[j] + ko));
        }
        CP_COMMIT();
    }

    int l = tid & 31;
    int w = tid >> 5;
    int mbase = (w >> 2) * 64;
    int nbase = (w & 3) * 32;
    int akey = l & 7;
    int ahib = l >> 4;
    uint32_t am128[4];
    #pragma unroll
    for (int mf = 0; mf < 4; mf++)
        am128[mf] = (uint32_t)((mbase + mf * 16 + (l & 15)) * 128);
    uint32_t bn128[4];
    #pragma unroll
    for (int nf = 0; nf < 4; nf++)
        bn128[nf] = (uint32_t)((nbase + nf * 8 + (l & 7)) * 128);
    uint32_t bq = (uint32_t)((l >> 3) & 3);

    float acc[4][4][4];
    #pragma unroll
    for (int i = 0; i < 4; i++)
        #pragma unroll
        for (int j = 0; j < 4; j++)
            #pragma unroll
            for (int k = 0; k < 4; k++) acc[i][j][k] = 0.0f;

    for (int c = 0; c < NCH; c++) {
        CP_WAIT1();
        __syncthreads();

        if (c + NSTAGE - 1 < NCH) {
            int cn = c + NSTAGE - 1;
            uint32_t ab = sb + (uint32_t)(cn % NSTAGE) * STAGE_BYTES;
            uint32_t bb = ab + 16384u;
            uint32_t ko = (uint32_t)cn * BK;
            #pragma unroll
            for (int j = 0; j < 4; j++) {
                cp_async16(ab + dsw[j], Asrc + (size_t)(aoff[j] + ko));
                cp_async16(bb + dsw[j], Wb + (size_t)(boff[j] + ko));
            }
        }
        CP_COMMIT();

        uint32_t ab = sb + (uint32_t)(c % NSTAGE) * STAGE_BYTES;
        uint32_t bb = ab + 16384u;
        #pragma unroll
        for (int p = 0; p < 2; p++) {
            uint32_t bf[4][4];
            #pragma unroll
            for (int nf = 0; nf < 4; nf++) {
                uint32_t slot = (((uint32_t)p << 2) | bq) ^ (uint32_t)akey;
                ldsm_x4(bf[nf], bb + bn128[nf] + (slot << 4));
            }
            #pragma unroll
            for (int sh = 0; sh < 2; sh++) {
                int s = 2 * p + sh;
                uint32_t af[4][4];
                #pragma unroll
                for (int mf = 0; mf < 4; mf++) {
                    uint32_t slot = (uint32_t)(((s << 1) | ahib) ^ akey);
                    ldsm_x4(af[mf], ab + am128[mf] + (slot << 4));
                }
                #pragma unroll
                for (int mf = 0; mf < 4; mf++)
                    #pragma unroll
                    for (int nf = 0; nf < 4; nf++)
                        mma_f16(acc[mf][nf], af[mf], &bf[nf][2 * sh]);
            }
        }
    }

    // ---- epilogue ----
    #pragma unroll
    for (int mf = 0; mf < 4; mf++) {
        int r0 = mbase + mf * 16 + (l >> 2);
        int r1 = r0 + 8;
        int a0 = sh_aidx[r0];
        int a1 = sh_aidx[r1];
        float w0 = GELU_EPI ? 1.0f : sh_wt[r0];
        float w1 = GELU_EPI ? 1.0f : sh_wt[r1];
        int t0 = a0 >> 1, t1 = a1 >> 1;
        #pragma unroll
        for (int nf = 0; nf < 4; nf++) {
            int cidx = nbase + nf * 8 + (l & 3) * 2;
            float b0c = sh_bias[cidx], b1c = sh_bias[cidx + 1];
            if (a0 >= 0) {
                float v0 = acc[mf][nf][0] + b0c;
                float v1 = acc[mf][nf][1] + b1c;
                if (GELU_EPI) {
                    __half2 hv = __floats2half2_rn(gelu_exact(v0), gelu_exact(v1));
                    *(__half2*)(g_H + (size_t)a0 * NOUT + n0 + cidx) = hv;
                } else {
                    red_add_v2(out_final + (size_t)t0 * NOUT + n0 + cidx,
                               v0 * w0, v1 * w0);
                }
            }
            if (a1 >= 0) {
                float v2 = acc[mf][nf][2] + b0c;
                float v3 = acc[mf][nf][3] + b1c;
                if (GELU_EPI) {
                    __half2 hv = __floats2half2_rn(gelu_exact(v2), gelu_exact(v3));
                    *(__half2*)(g_H + (size_t)a1 * NOUT + n0 + cidx) = hv;
                } else {
                    red_add_v2(out_final + (size_t)t1 * NOUT + n0 + cidx,
                               v2 * w1, v3 * w1);
                }
            }
        }
    }
}

// ---------------- streams/events for capture fork-join (created once at load) ----------------
static cudaStream_t s_prep = nullptr;
static cudaStream_t s_gate = nullptr;
static cudaEvent_t  ev_fork = nullptr, ev_prep = nullptr, ev_gate = nullptr;
static struct StreamInit {
    StreamInit() {
        cudaStreamCreateWithFlags(&s_prep, cudaStreamNonBlocking);
        cudaStreamCreateWithFlags(&s_gate, cudaStreamNonBlocking);
        cudaEventCreateWithFlags(&ev_fork, cudaEventDisableTiming);
        cudaEventCreateWithFlags(&ev_prep, cudaEventDisableTiming);
        cudaEventCreateWithFlags(&ev_gate, cudaEventDisableTiming);
    }
} s_init;

// ---------------- launch ----------------
extern "C" void kernel_launch(void* const* d_in, const int* in_sizes, int n_in,
                              void* d_out, int out_size) {
    const float* x  = (const float*)d_in[0];
    const float* Wg = (const float*)d_in[1];
    const float* W1 = (const float*)d_in[2];
    const float* b1 = (const float*)d_in[3];
    const float* W2 = (const float*)d_in[4];
    const float* b2 = (const float*)d_in[5];
    float* out = (float*)d_out;
    int N = in_sizes[0] / D_DIM;   // 8192

    cudaFuncSetAttribute(moe_mma_kernel<D_DIM, H_DIM, true>,
                         cudaFuncAttributeMaxDynamicSharedMemorySize, SMEM_DYN);
    cudaFuncSetAttribute(moe_mma_kernel<H_DIM, D_DIM, false>,
                         cudaFuncAttributeMaxDynamicSharedMemorySize, SMEM_DYN);

    __half* w1c; cudaGetSymbolAddress((void**)&w1c, g_W1c);
    __half* w2c; cudaGetSymbolAddress((void**)&w2c, g_W2c);
    __half* xc;  cudaGetSymbolAddress((void**)&xc,  g_Xc);
    __half* hbuf; cudaGetSymbolAddress((void**)&hbuf, g_H);
    int* cntp;  cudaGetSymbolAddress((void**)&cntp, g_cnt);

    // ---- fork ----
    cudaEventRecord(ev_fork, 0);
    cudaStreamWaitEvent(s_prep, ev_fork, 0);
    cudaStreamWaitEvent(s_gate, ev_fork, 0);

    // side stream A: W2 conversion + output zeroing (needed only by GEMM2)
    {
        int nblk = (int)(((long long)WN4 + 255) / 256);
        prep_w2_kernel<<<nblk, 256, 0, s_prep>>>((const float4*)W2, (__half2*)w2c);
        cudaMemsetAsync(out, 0, (size_t)out_size * sizeof(float), s_prep);
        cudaEventRecord(ev_prep, s_prep);
    }

    // side stream B: routing (zero counters, then gate)
    {
        cudaMemsetAsync(cntp, 0, E_NUM * sizeof(int), s_gate);
        gate_kernel<<<(N + 7) / 8, 256, 0, s_gate>>>(x, Wg, N);
        cudaEventRecord(ev_gate, s_gate);
    }

    // main stream: X+W1 conversion (GEMM1 inputs)
    {
        long long jobs = (long long)WN4 + XN4;
        int nblk = (int)((jobs + 255) / 256);
        prep_xw1_kernel<<<nblk, 256>>>((const float4*)W1, (const float4*)x,
                                       (__half2*)w1c, (__half2*)xc);
    }

    cudaStreamWaitEvent(0, ev_gate, 0);
    moe_mma_kernel<D_DIM, H_DIM, true >
        <<<dim3(H_DIM / BN, MBLKS, E_NUM), 256, SMEM_DYN>>>(xc, w1c, b1, nullptr);

    cudaStreamWaitEvent(0, ev_prep, 0);
    moe_mma_kernel<H_DIM, D_DIM, false>
        <<<dim3(D_DIM / BN, MBLKS, E_NUM), 256, SMEM_DYN>>>(hbuf, w2c, b2, out);
}